// round 9
// baseline (speedup 1.0000x reference)
#include <cuda_runtime.h>
#include <cstdint>

#define HEADS 6
#define HD 32
#define CDIM 192
#define NQ 576
#define DISP 4
#define IMG 256
#define BATCH 4
#define TOK 64
#define NWIN 1024
#define MTOT (BATCH * IMG * IMG)
#define ATT_SCALE 0.17677669529663687f

// scratch (allocation-free rule: __device__ globals)
__device__ float g_qkv[(size_t)MTOT * NQ];     // ROLLED coords, [m, 576]
__device__ float g_attn[(size_t)MTOT * CDIM];  // ROLLED coords, [m, 192]
__device__ float g_bias[TOK * TOK];

// ---------------------------------------------------------------------------
// mma.sync + cp.async helpers
// ---------------------------------------------------------------------------
__device__ __forceinline__ uint32_t f2tf32(float f) {
    uint32_t r;
    asm("cvt.rna.tf32.f32 %0, %1;" : "=r"(r) : "f"(f));
    return r;
}
__device__ __forceinline__ void mma_tf32(float* c, const uint32_t* a, const uint32_t* b) {
    asm volatile(
        "mma.sync.aligned.m16n8k8.row.col.f32.tf32.tf32.f32 "
        "{%0,%1,%2,%3}, {%4,%5,%6,%7}, {%8,%9}, {%0,%1,%2,%3};"
        : "+f"(c[0]), "+f"(c[1]), "+f"(c[2]), "+f"(c[3])
        : "r"(a[0]), "r"(a[1]), "r"(a[2]), "r"(a[3]), "r"(b[0]), "r"(b[1]));
}
__device__ __forceinline__ uint32_t smem_u32(const void* p) {
    uint32_t a;
    asm("{ .reg .u64 t; cvta.to.shared.u64 t, %1; cvt.u32.u64 %0, t; }" : "=r"(a) : "l"(p));
    return a;
}
__device__ __forceinline__ void cp_async16(uint32_t dst, const void* src) {
    asm volatile("cp.async.cg.shared.global [%0], [%1], 16;" :: "r"(dst), "l"(src));
}
#define CP_COMMIT() asm volatile("cp.async.commit_group;" ::: "memory")
#define CP_WAIT0()  asm volatile("cp.async.wait_group 0;" ::: "memory")

// GEMM tiles: BM=128, BN=64, K=192. 128 thr, 4 warps (2m x 2n), warp tile 64x32.
// smem: A[128][192] fp32 + 2 x B[64][192] fp32, XOR-chunk swizzle, no padding.
#define BM 128
#define BN 64
#define A_WORDS (BM * CDIM)                 // 24576 (98304 B)
#define B_WORDS (BN * CDIM)                 // 12288 (49152 B)
#define SMEM_BYTES ((A_WORDS + 2 * B_WORDS) * 4)   // 196608 B -> 1 CTA/SM

// word index of (row, k) under chunk swizzle: 16B chunk id ^= (row & 7)
__device__ __forceinline__ int swz(int row, int k) {
    return row * CDIM + ((((k >> 2) ^ (row & 7)) << 2) | (k & 3));
}

// ---------------------------------------------------------------------------
// Kernel 0: gather rel-pos bias table
// ---------------------------------------------------------------------------
__global__ void bias_kernel(const float* __restrict__ pos) {
    int idx = blockIdx.x * blockDim.x + threadIdx.x;
    if (idx < TOK * TOK) {
        int i = idx >> 6, j = idx & 63;
        g_bias[idx] = pos[((i >> 3) - (j >> 3) + 7) * 15 + ((i & 7) - (j & 7) + 7)];
    }
}

// ---------------------------------------------------------------------------
// Kernel 1: QKV GEMM. cp.async A + double-buffered B; cvt to tf32 in mainloop.
// Roll folded into A-load; g_qkv in ROLLED coords.
// ---------------------------------------------------------------------------
__global__ __launch_bounds__(128) void qkv_tc(const float* __restrict__ x,
                                              const float* __restrict__ wqkv) {
    extern __shared__ float sm[];
    float* As = sm;
    float* Bbuf[2] = { sm + A_WORDS, sm + A_WORDS + B_WORDS };
    uint32_t sbA = smem_u32(As);
    uint32_t sbB[2] = { smem_u32(Bbuf[0]), smem_u32(Bbuf[1]) };

    int tid = threadIdx.x;
    int wid = tid >> 5, lane = tid & 31;
    int warp_m = (wid >> 1) * 64;          // 2 m-warps x 64 rows
    int warp_n = (wid & 1) * 32;           // 2 n-warps x 32 cols
    int lr = lane >> 2, lc = lane & 3;
    int m0 = blockIdx.x * BM;

    // Prologue: async-load A (roll folded) and B tile 0.
    #pragma unroll
    for (int j = 0; j < 48; j++) {         // 6144 chunks / 128 thr
        int i = tid + j * 128;
        int r = i / 48, c = i % 48;        // row, 16B-chunk
        int m = m0 + r;
        int bb = m >> 16, y = (m >> 8) & 255, xx = m & 255;
        int ys = (y + DISP) & 255, xs = (xx + DISP) & 255;
        const float* src = x + ((size_t)((bb * IMG + ys) * IMG + xs)) * CDIM + c * 4;
        cp_async16(sbA + (uint32_t)(r * 768 + (c ^ (r & 7)) * 16), src);
    }
    #pragma unroll
    for (int j = 0; j < 24; j++) {         // 3072 chunks / 128 thr
        int i = tid + j * 128;
        int r = i / 48, c = i % 48;
        cp_async16(sbB[0] + (uint32_t)(r * 768 + (c ^ (r & 7)) * 16),
                   wqkv + (size_t)r * CDIM + c * 4);
    }
    CP_COMMIT();
    CP_WAIT0();
    __syncthreads();

    for (int t = 0; t < 9; t++) {
        int n0 = t * BN;
        // Issue next B tile into the other buffer (readers of it synced last iter).
        if (t < 8) {
            const float* wsrc = wqkv + (size_t)(n0 + BN) * CDIM;
            uint32_t dstb = sbB[(t + 1) & 1];
            #pragma unroll
            for (int j = 0; j < 24; j++) {
                int i = tid + j * 128;
                int r = i / 48, c = i % 48;
                cp_async16(dstb + (uint32_t)(r * 768 + (c ^ (r & 7)) * 16),
                           wsrc + (size_t)r * CDIM + c * 4);
            }
            CP_COMMIT();
        }

        const float* Bc = Bbuf[t & 1];
        float acc[4][4][4] = {};
        #pragma unroll 8
        for (int kk = 0; kk < 24; kk++) {
            int k0 = kk * 8;
            uint32_t a[4][4], b[4][2];
            #pragma unroll
            for (int mt = 0; mt < 4; mt++) {
                int row = warp_m + mt * 16 + lr;
                a[mt][0] = f2tf32(As[swz(row,     k0 + lc)]);
                a[mt][1] = f2tf32(As[swz(row + 8, k0 + lc)]);
                a[mt][2] = f2tf32(As[swz(row,     k0 + lc + 4)]);
                a[mt][3] = f2tf32(As[swz(row + 8, k0 + lc + 4)]);
            }
            #pragma unroll
            for (int nt = 0; nt < 4; nt++) {
                int col = warp_n + nt * 8 + lr;
                b[nt][0] = f2tf32(Bc[swz(col, k0 + lc)]);
                b[nt][1] = f2tf32(Bc[swz(col, k0 + lc + 4)]);
            }
            #pragma unroll
            for (int mt = 0; mt < 4; mt++)
                #pragma unroll
                for (int nt = 0; nt < 4; nt++)
                    mma_tf32(acc[mt][nt], a[mt], b[nt]);
        }

        // Epilogue: natural [m][576] layout.
        #pragma unroll
        for (int mt = 0; mt < 4; mt++) {
            size_t r0 = (size_t)(m0 + warp_m + mt * 16 + lr) * NQ + n0 + warp_n;
            size_t r1 = r0 + 8 * NQ;
            #pragma unroll
            for (int nt = 0; nt < 4; nt++) {
                int col = nt * 8 + lc * 2;
                *(float2*)(g_qkv + r0 + col) = make_float2(acc[mt][nt][0], acc[mt][nt][1]);
                *(float2*)(g_qkv + r1 + col) = make_float2(acc[mt][nt][2], acc[mt][nt][3]);
            }
        }

        if (t < 8) {
            CP_WAIT0();
            __syncthreads();
        }
    }
}

// ---------------------------------------------------------------------------
// Kernel 2: windowed attention via HMMA (unchanged from round 7).
// ---------------------------------------------------------------------------
#define QST 36
#define PST 68
#define BST 68

__global__ __launch_bounds__(128) void attn_mma() {
    __shared__ float pool[64 * QST * 2];
    __shared__ float vt[32 * PST];
    __shared__ float bsm[64 * BST];

    uint32_t* Qs = (uint32_t*)pool;
    uint32_t* Ks = (uint32_t*)pool + 64 * QST;
    uint32_t* Ps = (uint32_t*)pool;
    uint32_t* VT = (uint32_t*)vt;

    int bid = blockIdx.x;
    int head = bid % HEADS;
    int t2 = bid / HEADS;
    int win = t2 & (NWIN - 1);
    int bb = t2 >> 10;
    int wy = win >> 5, wx = win & 31;

    int tid = threadIdx.x;
    int wid = tid >> 5, lane = tid & 31;
    int lr = lane >> 2, lc = lane & 3;
    int r_base = wid * 16;

    #pragma unroll
    for (int l = 0; l < 4; l++) {
        int idx = tid + l * 128;
        int j = idx >> 3, d4 = idx & 7;
        int y = wy * 8 + (j >> 3), xx = wx * 8 + (j & 7);
        size_t base = ((size_t)((bb * IMG + y) * IMG + xx)) * NQ + head * HD + d4 * 4;
        float4 q = *(const float4*)(g_qkv + base);
        float4 k = *(const float4*)(g_qkv + base + CDIM);
        float4 v = *(const float4*)(g_qkv + base + 2 * CDIM);
        Qs[j * QST + d4 * 4 + 0] = f2tf32(q.x); Qs[j * QST + d4 * 4 + 1] = f2tf32(q.y);
        Qs[j * QST + d4 * 4 + 2] = f2tf32(q.z); Qs[j * QST + d4 * 4 + 3] = f2tf32(q.w);
        Ks[j * QST + d4 * 4 + 0] = f2tf32(k.x); Ks[j * QST + d4 * 4 + 1] = f2tf32(k.y);
        Ks[j * QST + d4 * 4 + 2] = f2tf32(k.z); Ks[j * QST + d4 * 4 + 3] = f2tf32(k.w);
        VT[(d4 * 4 + 0) * PST + j] = f2tf32(v.x);
        VT[(d4 * 4 + 1) * PST + j] = f2tf32(v.y);
        VT[(d4 * 4 + 2) * PST + j] = f2tf32(v.z);
        VT[(d4 * 4 + 3) * PST + j] = f2tf32(v.w);
    }
    #pragma unroll
    for (int l = 0; l < 8; l++) {
        int w0 = (tid + l * 128) * 4;
        int row = w0 >> 6, col = w0 & 63;
        float4 v = *(const float4*)(g_bias + w0);
        *(float4*)(bsm + row * BST + col) = v;
    }
    __syncthreads();

    uint32_t a[4][4];
    #pragma unroll
    for (int kk = 0; kk < 4; kk++) {
        int k0 = kk * 8;
        a[kk][0] = Qs[(r_base + lr) * QST + k0 + lc];
        a[kk][1] = Qs[(r_base + 8 + lr) * QST + k0 + lc];
        a[kk][2] = Qs[(r_base + lr) * QST + k0 + lc + 4];
        a[kk][3] = Qs[(r_base + 8 + lr) * QST + k0 + lc + 4];
    }
    float s[8][4] = {};
    #pragma unroll
    for (int nt = 0; nt < 8; nt++) {
        #pragma unroll
        for (int kk = 0; kk < 4; kk++) {
            int k0 = kk * 8;
            uint32_t b[2];
            b[0] = Ks[(nt * 8 + lr) * QST + k0 + lc];
            b[1] = Ks[(nt * 8 + lr) * QST + k0 + lc + 4];
            mma_tf32(s[nt], a[kk], b);
        }
    }
    int row0 = r_base + lr, row1 = r_base + lr + 8;
    #pragma unroll
    for (int nt = 0; nt < 8; nt++) {
        int col = nt * 8 + lc * 2;
        float2 b0 = *(const float2*)(bsm + row0 * BST + col);
        float2 b1 = *(const float2*)(bsm + row1 * BST + col);
        s[nt][0] = s[nt][0] * ATT_SCALE + b0.x;
        s[nt][1] = s[nt][1] * ATT_SCALE + b0.y;
        s[nt][2] = s[nt][2] * ATT_SCALE + b1.x;
        s[nt][3] = s[nt][3] * ATT_SCALE + b1.y;
    }

    float mx0 = -1e30f, mx1 = -1e30f;
    #pragma unroll
    for (int nt = 0; nt < 8; nt++) {
        mx0 = fmaxf(mx0, fmaxf(s[nt][0], s[nt][1]));
        mx1 = fmaxf(mx1, fmaxf(s[nt][2], s[nt][3]));
    }
    mx0 = fmaxf(mx0, __shfl_xor_sync(0xffffffff, mx0, 1));
    mx0 = fmaxf(mx0, __shfl_xor_sync(0xffffffff, mx0, 2));
    mx1 = fmaxf(mx1, __shfl_xor_sync(0xffffffff, mx1, 1));
    mx1 = fmaxf(mx1, __shfl_xor_sync(0xffffffff, mx1, 2));
    float sum0 = 0.f, sum1 = 0.f;
    #pragma unroll
    for (int nt = 0; nt < 8; nt++) {
        s[nt][0] = __expf(s[nt][0] - mx0); sum0 += s[nt][0];
        s[nt][1] = __expf(s[nt][1] - mx0); sum0 += s[nt][1];
        s[nt][2] = __expf(s[nt][2] - mx1); sum1 += s[nt][2];
        s[nt][3] = __expf(s[nt][3] - mx1); sum1 += s[nt][3];
    }
    sum0 += __shfl_xor_sync(0xffffffff, sum0, 1);
    sum0 += __shfl_xor_sync(0xffffffff, sum0, 2);
    sum1 += __shfl_xor_sync(0xffffffff, sum1, 1);
    sum1 += __shfl_xor_sync(0xffffffff, sum1, 2);
    float inv0 = 1.f / sum0, inv1 = 1.f / sum1;

    __syncthreads();
    #pragma unroll
    for (int nt = 0; nt < 8; nt++) {
        int col = nt * 8 + lc * 2;
        Ps[row0 * PST + col]     = f2tf32(s[nt][0]);
        Ps[row0 * PST + col + 1] = f2tf32(s[nt][1]);
        Ps[row1 * PST + col]     = f2tf32(s[nt][2]);
        Ps[row1 * PST + col + 1] = f2tf32(s[nt][3]);
    }
    __syncwarp();

    float o[4][4] = {};
    #pragma unroll
    for (int kk = 0; kk < 8; kk++) {
        int k0 = kk * 8;
        uint32_t ap[4];
        ap[0] = Ps[(r_base + lr) * PST + k0 + lc];
        ap[1] = Ps[(r_base + 8 + lr) * PST + k0 + lc];
        ap[2] = Ps[(r_base + lr) * PST + k0 + lc + 4];
        ap[3] = Ps[(r_base + 8 + lr) * PST + k0 + lc + 4];
        #pragma unroll
        for (int nt = 0; nt < 4; nt++) {
            uint32_t b[2];
            b[0] = VT[(nt * 8 + lr) * PST + k0 + lc];
            b[1] = VT[(nt * 8 + lr) * PST + k0 + lc + 4];
            mma_tf32(o[nt], ap, b);
        }
    }

    {
        int i0 = r_base + lr;
        int y0 = wy * 8 + (i0 >> 3), x0 = wx * 8 + (i0 & 7);
        int i1 = i0 + 8;
        int y1 = wy * 8 + (i1 >> 3), x1 = wx * 8 + (i1 & 7);
        float* p0 = g_attn + ((size_t)((bb * IMG + y0) * IMG + x0)) * CDIM + head * HD;
        float* p1 = g_attn + ((size_t)((bb * IMG + y1) * IMG + x1)) * CDIM + head * HD;
        #pragma unroll
        for (int nt = 0; nt < 4; nt++) {
            int col = nt * 8 + lc * 2;
            *(float2*)(p0 + col) = make_float2(o[nt][0] * inv0, o[nt][1] * inv0);
            *(float2*)(p1 + col) = make_float2(o[nt][2] * inv1, o[nt][3] * inv1);
        }
    }
}

// ---------------------------------------------------------------------------
// Kernel 3: output projection + bias; roll-back on store. Same GEMM shape.
// ---------------------------------------------------------------------------
__global__ __launch_bounds__(128) void out_tc(const float* __restrict__ wout,
                                              const float* __restrict__ bout,
                                              float* __restrict__ out) {
    extern __shared__ float sm[];
    float* As = sm;
    float* Bbuf[2] = { sm + A_WORDS, sm + A_WORDS + B_WORDS };
    uint32_t sbA = smem_u32(As);
    uint32_t sbB[2] = { smem_u32(Bbuf[0]), smem_u32(Bbuf[1]) };

    int tid = threadIdx.x;
    int wid = tid >> 5, lane = tid & 31;
    int warp_m = (wid >> 1) * 64;
    int warp_n = (wid & 1) * 32;
    int lr = lane >> 2, lc = lane & 3;
    int m0 = blockIdx.x * BM;

    #pragma unroll
    for (int j = 0; j < 48; j++) {
        int i = tid + j * 128;
        int r = i / 48, c = i % 48;
        cp_async16(sbA + (uint32_t)(r * 768 + (c ^ (r & 7)) * 16),
                   g_attn + (size_t)(m0 + r) * CDIM + c * 4);
    }
    #pragma unroll
    for (int j = 0; j < 24; j++) {
        int i = tid + j * 128;
        int r = i / 48, c = i % 48;
        cp_async16(sbB[0] + (uint32_t)(r * 768 + (c ^ (r & 7)) * 16),
                   wout + (size_t)r * CDIM + c * 4);
    }
    CP_COMMIT();
    CP_WAIT0();
    __syncthreads();

    for (int t = 0; t < 3; t++) {
        int n0 = t * BN;
        if (t < 2) {
            const float* wsrc = wout + (size_t)(n0 + BN) * CDIM;
            uint32_t dstb = sbB[(t + 1) & 1];
            #pragma unroll
            for (int j = 0; j < 24; j++) {
                int i = tid + j * 128;
                int r = i / 48, c = i % 48;
                cp_async16(dstb + (uint32_t)(r * 768 + (c ^ (r & 7)) * 16),
                           wsrc + (size_t)r * CDIM + c * 4);
            }
            CP_COMMIT();
        }

        const float* Bc = Bbuf[t & 1];
        float acc[4][4][4] = {};
        #pragma unroll 8
        for (int kk = 0; kk < 24; kk++) {
            int k0 = kk * 8;
            uint32_t a[4][4], b[4][2];
            #pragma unroll
            for (int mt = 0; mt < 4; mt++) {
                int row = warp_m + mt * 16 + lr;
                a[mt][0] = f2tf32(As[swz(row,     k0 + lc)]);
                a[mt][1] = f2tf32(As[swz(row + 8, k0 + lc)]);
                a[mt][2] = f2tf32(As[swz(row,     k0 + lc + 4)]);
                a[mt][3] = f2tf32(As[swz(row + 8, k0 + lc + 4)]);
            }
            #pragma unroll
            for (int nt = 0; nt < 4; nt++) {
                int col = warp_n + nt * 8 + lr;
                b[nt][0] = f2tf32(Bc[swz(col, k0 + lc)]);
                b[nt][1] = f2tf32(Bc[swz(col, k0 + lc + 4)]);
            }
            #pragma unroll
            for (int mt = 0; mt < 4; mt++)
                #pragma unroll
                for (int nt = 0; nt < 4; nt++)
                    mma_tf32(acc[mt][nt], a[mt], b[nt]);
        }

        #pragma unroll
        for (int mt = 0; mt < 4; mt++) {
            #pragma unroll
            for (int half = 0; half < 2; half++) {
                int m = m0 + warp_m + mt * 16 + lr + half * 8;
                int bb = m >> 16, y = (m >> 8) & 255, xx = m & 255;
                int yf = (y + DISP) & 255, xf = (xx + DISP) & 255;
                float* op = out + ((size_t)(bb * IMG + yf) * IMG + xf) * CDIM + n0 + warp_n;
                #pragma unroll
                for (int nt = 0; nt < 4; nt++) {
                    int col = nt * 8 + lc * 2;
                    float b0 = bout[n0 + warp_n + col];
                    float b1 = bout[n0 + warp_n + col + 1];
                    *(float2*)(op + col) = make_float2(acc[mt][nt][half * 2] + b0,
                                                       acc[mt][nt][half * 2 + 1] + b1);
                }
            }
        }

        if (t < 2) {
            CP_WAIT0();
            __syncthreads();
        }
    }
}

// ---------------------------------------------------------------------------
extern "C" void kernel_launch(void* const* d_in, const int* in_sizes, int n_in,
                              void* d_out, int out_size) {
    const float* x    = (const float*)d_in[0];
    const float* wqkv = (const float*)d_in[1];
    const float* pos  = (const float*)d_in[2];
    const float* wout = (const float*)d_in[3];
    const float* bout = (const float*)d_in[4];
    float* out = (float*)d_out;

    cudaFuncSetAttribute(qkv_tc, cudaFuncAttributeMaxDynamicSharedMemorySize, SMEM_BYTES);
    cudaFuncSetAttribute(out_tc, cudaFuncAttributeMaxDynamicSharedMemorySize, SMEM_BYTES);

    bias_kernel<<<16, 256>>>(pos);
    qkv_tc<<<MTOT / BM, 128, SMEM_BYTES>>>(x, wqkv);
    attn_mma<<<BATCH * NWIN * HEADS, 128>>>();
    out_tc<<<MTOT / BM, 128, SMEM_BYTES>>>(wout, bout, out);
}

// round 10
// speedup vs baseline: 1.3624x; 1.3624x over previous
#include <cuda_runtime.h>
#include <cstdint>

#define HEADS 6
#define HD 32
#define CDIM 192
#define NQ 576
#define DISP 4
#define IMG 256
#define BATCH 4
#define TOK 64
#define NWIN 1024
#define MTOT (BATCH * IMG * IMG)
#define ATT_SCALE 0.17677669529663687f

// scratch (allocation-free rule: __device__ globals)
__device__ float g_qkv[(size_t)MTOT * NQ];     // ROLLED coords, [m, 576]
__device__ float g_attn[(size_t)MTOT * CDIM];  // ROLLED coords, [m, 192]
__device__ float g_bias[TOK * TOK];

// ---------------------------------------------------------------------------
// mma.sync / ldmatrix helpers
// ---------------------------------------------------------------------------
__device__ __forceinline__ uint32_t f2tf32(float f) {
    uint32_t r;
    asm("cvt.rna.tf32.f32 %0, %1;" : "=r"(r) : "f"(f));
    return r;
}
__device__ __forceinline__ void mma_tf32(float* c, const uint32_t* a, const uint32_t* b) {
    asm volatile(
        "mma.sync.aligned.m16n8k8.row.col.f32.tf32.tf32.f32 "
        "{%0,%1,%2,%3}, {%4,%5,%6,%7}, {%8,%9}, {%0,%1,%2,%3};"
        : "+f"(c[0]), "+f"(c[1]), "+f"(c[2]), "+f"(c[3])
        : "r"(a[0]), "r"(a[1]), "r"(a[2]), "r"(a[3]), "r"(b[0]), "r"(b[1]));
}
__device__ __forceinline__ uint32_t smem_u32(const void* p) {
    uint32_t a;
    asm("{ .reg .u64 t; cvta.to.shared.u64 t, %1; cvt.u32.u64 %0, t; }" : "=r"(a) : "l"(p));
    return a;
}
// 4x (8x8 b32) matrices per call; lane-distribution matches tf32 mma fragments.
__device__ __forceinline__ void ldsm_x4(uint32_t* r, uint32_t addr) {
    asm volatile("ldmatrix.sync.aligned.m8n8.x4.shared.b16 {%0,%1,%2,%3}, [%4];"
                 : "=r"(r[0]), "=r"(r[1]), "=r"(r[2]), "=r"(r[3]) : "r"(addr));
}

// GEMM smem: BM=64 rows A + 64 rows B, stride 196 words.
// 196/4 = 49 ≡ 1 (mod 8) -> ldmatrix 8-row gathers hit distinct bank-quads.
#define AST 196
#define A_WORDS (64 * AST)
#define SMEM_BYTES (2 * A_WORDS * 4)   // 100352 B -> 2 CTAs/SM

// ---------------------------------------------------------------------------
// Kernel 0: gather rel-pos bias table
// ---------------------------------------------------------------------------
__global__ void bias_kernel(const float* __restrict__ pos) {
    int idx = blockIdx.x * blockDim.x + threadIdx.x;
    if (idx < TOK * TOK) {
        int i = idx >> 6, j = idx & 63;
        g_bias[idx] = pos[((i >> 3) - (j >> 3) + 7) * 15 + ((i & 7) - (j & 7) + 7)];
    }
}

// ---------------------------------------------------------------------------
// Kernel 1: QKV GEMM. BM=64, 128 thr, 4 warps (2m x 2n), warp tile 32x32.
// Fragment loads via ldmatrix.x4 (4 instr per k-step instead of 16 LDS).
// Roll folded into A-load; g_qkv in ROLLED coords.
// ---------------------------------------------------------------------------
__global__ __launch_bounds__(128) void qkv_tc(const float* __restrict__ x,
                                              const float* __restrict__ wqkv) {
    extern __shared__ uint32_t sm[];
    uint32_t* As = sm;
    uint32_t* Bs = sm + A_WORDS;
    uint32_t sbase = smem_u32(sm);

    int tid = threadIdx.x;
    int wid = tid >> 5, lane = tid & 31;
    int warp_m = (wid >> 1) * 32;
    int warp_n = (wid & 1) * 32;
    int lr = lane >> 2, lc = lane & 3;
    int m0 = blockIdx.x * 64;

    // ldmatrix per-lane base byte-offsets.
    int lrow  = lane & 7;
    int lsel8 = (lane >> 3) & 1;   // matrix row-half selector
    int lsel16 = (lane >> 4) & 1;  // matrix k-half / n-half selector
    // A: m0=(rows+0,klo) m1=(rows+8,klo+?)... lanes: 0-7 a0, 8-15 a1(+8 rows), 16-23 a2(k+4), 24-31 a3
    uint32_t aoff0 = sbase + (uint32_t)(((warp_m + lrow + lsel8 * 8) * AST + lsel16 * 4) * 4);
    uint32_t aoff1 = aoff0 + 16 * AST * 4;
    // B: p covers nt pair: lanes 0-7 b[2p][0], 8-15 b[2p][1](k+4), 16-31 nt+1 (+8 cols)
    uint32_t boff0 = sbase + (uint32_t)(A_WORDS * 4) +
                     (uint32_t)(((warp_n + lrow + lsel16 * 8) * AST + lsel8 * 4) * 4);
    uint32_t boff1 = boff0 + 16 * AST * 4;

    // A tile 64x192, roll folded in. 3072 float4 / 128 thr = 24 each.
    #pragma unroll
    for (int j = 0; j < 24; j++) {
        int i = tid + j * 128;
        int r = i / 48, c4 = i % 48;
        int m = m0 + r;
        int bb = m >> 16, y = (m >> 8) & 255, xx = m & 255;
        int ys = (y + DISP) & 255, xs = (xx + DISP) & 255;
        float4 v = *(const float4*)(x + ((size_t)((bb * IMG + ys) * IMG + xs)) * CDIM + c4 * 4);
        *(uint4*)&As[r * AST + c4 * 4] =
            make_uint4(f2tf32(v.x), f2tf32(v.y), f2tf32(v.z), f2tf32(v.w));
    }

    for (int t = 0; t < 9; t++) {
        int n0 = t * 64;
        __syncthreads();   // prev-tile readers done (covers A-load on t=0 too)
        #pragma unroll
        for (int j = 0; j < 24; j++) {
            int i = tid + j * 128;
            int r = i / 48, c4 = i % 48;
            float4 v = *(const float4*)(wqkv + (size_t)(n0 + r) * CDIM + c4 * 4);
            *(uint4*)&Bs[r * AST + c4 * 4] =
                make_uint4(f2tf32(v.x), f2tf32(v.y), f2tf32(v.z), f2tf32(v.w));
        }
        __syncthreads();

        float acc[2][4][4] = {};
        #pragma unroll
        for (int kk = 0; kk < 24; kk++) {
            uint32_t kb = (uint32_t)(kk * 8 * 4);   // k0 bytes
            uint32_t a0[4], a1[4], b0[4], b1[4];
            ldsm_x4(a0, aoff0 + kb);
            ldsm_x4(a1, aoff1 + kb);
            ldsm_x4(b0, boff0 + kb);
            ldsm_x4(b1, boff1 + kb);
            mma_tf32(acc[0][0], a0, b0);     mma_tf32(acc[0][1], a0, b0 + 2);
            mma_tf32(acc[0][2], a0, b1);     mma_tf32(acc[0][3], a0, b1 + 2);
            mma_tf32(acc[1][0], a1, b0);     mma_tf32(acc[1][1], a1, b0 + 2);
            mma_tf32(acc[1][2], a1, b1);     mma_tf32(acc[1][3], a1, b1 + 2);
        }

        #pragma unroll
        for (int mt = 0; mt < 2; mt++) {
            size_t r0 = (size_t)(m0 + warp_m + mt * 16 + lr) * NQ + n0 + warp_n;
            size_t r1 = r0 + 8 * NQ;
            #pragma unroll
            for (int nt = 0; nt < 4; nt++) {
                int col = nt * 8 + lc * 2;
                *(float2*)(g_qkv + r0 + col) = make_float2(acc[mt][nt][0], acc[mt][nt][1]);
                *(float2*)(g_qkv + r1 + col) = make_float2(acc[mt][nt][2], acc[mt][nt][3]);
            }
        }
    }
}

// ---------------------------------------------------------------------------
// Kernel 2: windowed attention via HMMA (unchanged from round 7).
// ---------------------------------------------------------------------------
#define QST 36
#define PST 68
#define BST 68

__global__ __launch_bounds__(128) void attn_mma() {
    __shared__ float pool[64 * QST * 2];
    __shared__ float vt[32 * PST];
    __shared__ float bsm[64 * BST];

    uint32_t* Qs = (uint32_t*)pool;
    uint32_t* Ks = (uint32_t*)pool + 64 * QST;
    uint32_t* Ps = (uint32_t*)pool;
    uint32_t* VT = (uint32_t*)vt;

    int bid = blockIdx.x;
    int head = bid % HEADS;
    int t2 = bid / HEADS;
    int win = t2 & (NWIN - 1);
    int bb = t2 >> 10;
    int wy = win >> 5, wx = win & 31;

    int tid = threadIdx.x;
    int wid = tid >> 5, lane = tid & 31;
    int lr = lane >> 2, lc = lane & 3;
    int r_base = wid * 16;

    #pragma unroll
    for (int l = 0; l < 4; l++) {
        int idx = tid + l * 128;
        int j = idx >> 3, d4 = idx & 7;
        int y = wy * 8 + (j >> 3), xx = wx * 8 + (j & 7);
        size_t base = ((size_t)((bb * IMG + y) * IMG + xx)) * NQ + head * HD + d4 * 4;
        float4 q = *(const float4*)(g_qkv + base);
        float4 k = *(const float4*)(g_qkv + base + CDIM);
        float4 v = *(const float4*)(g_qkv + base + 2 * CDIM);
        Qs[j * QST + d4 * 4 + 0] = f2tf32(q.x); Qs[j * QST + d4 * 4 + 1] = f2tf32(q.y);
        Qs[j * QST + d4 * 4 + 2] = f2tf32(q.z); Qs[j * QST + d4 * 4 + 3] = f2tf32(q.w);
        Ks[j * QST + d4 * 4 + 0] = f2tf32(k.x); Ks[j * QST + d4 * 4 + 1] = f2tf32(k.y);
        Ks[j * QST + d4 * 4 + 2] = f2tf32(k.z); Ks[j * QST + d4 * 4 + 3] = f2tf32(k.w);
        VT[(d4 * 4 + 0) * PST + j] = f2tf32(v.x);
        VT[(d4 * 4 + 1) * PST + j] = f2tf32(v.y);
        VT[(d4 * 4 + 2) * PST + j] = f2tf32(v.z);
        VT[(d4 * 4 + 3) * PST + j] = f2tf32(v.w);
    }
    #pragma unroll
    for (int l = 0; l < 8; l++) {
        int w0 = (tid + l * 128) * 4;
        int row = w0 >> 6, col = w0 & 63;
        float4 v = *(const float4*)(g_bias + w0);
        *(float4*)(bsm + row * BST + col) = v;
    }
    __syncthreads();

    uint32_t a[4][4];
    #pragma unroll
    for (int kk = 0; kk < 4; kk++) {
        int k0 = kk * 8;
        a[kk][0] = Qs[(r_base + lr) * QST + k0 + lc];
        a[kk][1] = Qs[(r_base + 8 + lr) * QST + k0 + lc];
        a[kk][2] = Qs[(r_base + lr) * QST + k0 + lc + 4];
        a[kk][3] = Qs[(r_base + 8 + lr) * QST + k0 + lc + 4];
    }
    float s[8][4] = {};
    #pragma unroll
    for (int nt = 0; nt < 8; nt++) {
        #pragma unroll
        for (int kk = 0; kk < 4; kk++) {
            int k0 = kk * 8;
            uint32_t b[2];
            b[0] = Ks[(nt * 8 + lr) * QST + k0 + lc];
            b[1] = Ks[(nt * 8 + lr) * QST + k0 + lc + 4];
            mma_tf32(s[nt], a[kk], b);
        }
    }
    int row0 = r_base + lr, row1 = r_base + lr + 8;
    #pragma unroll
    for (int nt = 0; nt < 8; nt++) {
        int col = nt * 8 + lc * 2;
        float2 b0 = *(const float2*)(bsm + row0 * BST + col);
        float2 b1 = *(const float2*)(bsm + row1 * BST + col);
        s[nt][0] = s[nt][0] * ATT_SCALE + b0.x;
        s[nt][1] = s[nt][1] * ATT_SCALE + b0.y;
        s[nt][2] = s[nt][2] * ATT_SCALE + b1.x;
        s[nt][3] = s[nt][3] * ATT_SCALE + b1.y;
    }

    float mx0 = -1e30f, mx1 = -1e30f;
    #pragma unroll
    for (int nt = 0; nt < 8; nt++) {
        mx0 = fmaxf(mx0, fmaxf(s[nt][0], s[nt][1]));
        mx1 = fmaxf(mx1, fmaxf(s[nt][2], s[nt][3]));
    }
    mx0 = fmaxf(mx0, __shfl_xor_sync(0xffffffff, mx0, 1));
    mx0 = fmaxf(mx0, __shfl_xor_sync(0xffffffff, mx0, 2));
    mx1 = fmaxf(mx1, __shfl_xor_sync(0xffffffff, mx1, 1));
    mx1 = fmaxf(mx1, __shfl_xor_sync(0xffffffff, mx1, 2));
    float sum0 = 0.f, sum1 = 0.f;
    #pragma unroll
    for (int nt = 0; nt < 8; nt++) {
        s[nt][0] = __expf(s[nt][0] - mx0); sum0 += s[nt][0];
        s[nt][1] = __expf(s[nt][1] - mx0); sum0 += s[nt][1];
        s[nt][2] = __expf(s[nt][2] - mx1); sum1 += s[nt][2];
        s[nt][3] = __expf(s[nt][3] - mx1); sum1 += s[nt][3];
    }
    sum0 += __shfl_xor_sync(0xffffffff, sum0, 1);
    sum0 += __shfl_xor_sync(0xffffffff, sum0, 2);
    sum1 += __shfl_xor_sync(0xffffffff, sum1, 1);
    sum1 += __shfl_xor_sync(0xffffffff, sum1, 2);
    float inv0 = 1.f / sum0, inv1 = 1.f / sum1;

    __syncthreads();
    #pragma unroll
    for (int nt = 0; nt < 8; nt++) {
        int col = nt * 8 + lc * 2;
        Ps[row0 * PST + col]     = f2tf32(s[nt][0]);
        Ps[row0 * PST + col + 1] = f2tf32(s[nt][1]);
        Ps[row1 * PST + col]     = f2tf32(s[nt][2]);
        Ps[row1 * PST + col + 1] = f2tf32(s[nt][3]);
    }
    __syncwarp();

    float o[4][4] = {};
    #pragma unroll
    for (int kk = 0; kk < 8; kk++) {
        int k0 = kk * 8;
        uint32_t ap[4];
        ap[0] = Ps[(r_base + lr) * PST + k0 + lc];
        ap[1] = Ps[(r_base + 8 + lr) * PST + k0 + lc];
        ap[2] = Ps[(r_base + lr) * PST + k0 + lc + 4];
        ap[3] = Ps[(r_base + 8 + lr) * PST + k0 + lc + 4];
        #pragma unroll
        for (int nt = 0; nt < 4; nt++) {
            uint32_t b[2];
            b[0] = VT[(nt * 8 + lr) * PST + k0 + lc];
            b[1] = VT[(nt * 8 + lr) * PST + k0 + lc + 4];
            mma_tf32(o[nt], ap, b);
        }
    }

    {
        int i0 = r_base + lr;
        int y0 = wy * 8 + (i0 >> 3), x0 = wx * 8 + (i0 & 7);
        int i1 = i0 + 8;
        int y1 = wy * 8 + (i1 >> 3), x1 = wx * 8 + (i1 & 7);
        float* p0 = g_attn + ((size_t)((bb * IMG + y0) * IMG + x0)) * CDIM + head * HD;
        float* p1 = g_attn + ((size_t)((bb * IMG + y1) * IMG + x1)) * CDIM + head * HD;
        #pragma unroll
        for (int nt = 0; nt < 4; nt++) {
            int col = nt * 8 + lc * 2;
            *(float2*)(p0 + col) = make_float2(o[nt][0] * inv0, o[nt][1] * inv0);
            *(float2*)(p1 + col) = make_float2(o[nt][2] * inv1, o[nt][3] * inv1);
        }
    }
}

// ---------------------------------------------------------------------------
// Kernel 3: output projection + bias; roll-back on store. BM=64, 128 thr.
// ldmatrix fragment loads (same mechanics as qkv_tc).
// ---------------------------------------------------------------------------
__global__ __launch_bounds__(128) void out_tc(const float* __restrict__ wout,
                                              const float* __restrict__ bout,
                                              float* __restrict__ out) {
    extern __shared__ uint32_t sm[];
    uint32_t* As = sm;
    uint32_t* Bs = sm + A_WORDS;
    uint32_t sbase = smem_u32(sm);

    int tid = threadIdx.x;
    int wid = tid >> 5, lane = tid & 31;
    int warp_m = (wid >> 1) * 32;
    int warp_n = (wid & 1) * 32;
    int lr = lane >> 2, lc = lane & 3;
    int m0 = blockIdx.x * 64;

    int lrow  = lane & 7;
    int lsel8 = (lane >> 3) & 1;
    int lsel16 = (lane >> 4) & 1;
    uint32_t aoff0 = sbase + (uint32_t)(((warp_m + lrow + lsel8 * 8) * AST + lsel16 * 4) * 4);
    uint32_t aoff1 = aoff0 + 16 * AST * 4;
    uint32_t boff0 = sbase + (uint32_t)(A_WORDS * 4) +
                     (uint32_t)(((warp_n + lrow + lsel16 * 8) * AST + lsel8 * 4) * 4);
    uint32_t boff1 = boff0 + 16 * AST * 4;

    #pragma unroll
    for (int j = 0; j < 24; j++) {
        int i = tid + j * 128;
        int r = i / 48, c4 = i % 48;
        float4 v = *(const float4*)(g_attn + (size_t)(m0 + r) * CDIM + c4 * 4);
        *(uint4*)&As[r * AST + c4 * 4] =
            make_uint4(f2tf32(v.x), f2tf32(v.y), f2tf32(v.z), f2tf32(v.w));
    }

    for (int t = 0; t < 3; t++) {
        int n0 = t * 64;
        __syncthreads();
        #pragma unroll
        for (int j = 0; j < 24; j++) {
            int i = tid + j * 128;
            int r = i / 48, c4 = i % 48;
            float4 v = *(const float4*)(wout + (size_t)(n0 + r) * CDIM + c4 * 4);
            *(uint4*)&Bs[r * AST + c4 * 4] =
                make_uint4(f2tf32(v.x), f2tf32(v.y), f2tf32(v.z), f2tf32(v.w));
        }
        __syncthreads();

        float acc[2][4][4] = {};
        #pragma unroll
        for (int kk = 0; kk < 24; kk++) {
            uint32_t kb = (uint32_t)(kk * 8 * 4);
            uint32_t a0[4], a1[4], b0[4], b1[4];
            ldsm_x4(a0, aoff0 + kb);
            ldsm_x4(a1, aoff1 + kb);
            ldsm_x4(b0, boff0 + kb);
            ldsm_x4(b1, boff1 + kb);
            mma_tf32(acc[0][0], a0, b0);     mma_tf32(acc[0][1], a0, b0 + 2);
            mma_tf32(acc[0][2], a0, b1);     mma_tf32(acc[0][3], a0, b1 + 2);
            mma_tf32(acc[1][0], a1, b0);     mma_tf32(acc[1][1], a1, b0 + 2);
            mma_tf32(acc[1][2], a1, b1);     mma_tf32(acc[1][3], a1, b1 + 2);
        }

        #pragma unroll
        for (int mt = 0; mt < 2; mt++) {
            #pragma unroll
            for (int half = 0; half < 2; half++) {
                int m = m0 + warp_m + mt * 16 + lr + half * 8;
                int bb = m >> 16, y = (m >> 8) & 255, xx = m & 255;
                int yf = (y + DISP) & 255, xf = (xx + DISP) & 255;
                float* op = out + ((size_t)(bb * IMG + yf) * IMG + xf) * CDIM + n0 + warp_n;
                #pragma unroll
                for (int nt = 0; nt < 4; nt++) {
                    int col = nt * 8 + lc * 2;
                    float b0v = bout[n0 + warp_n + col];
                    float b1v = bout[n0 + warp_n + col + 1];
                    *(float2*)(op + col) = make_float2(acc[mt][nt][half * 2] + b0v,
                                                       acc[mt][nt][half * 2 + 1] + b1v);
                }
            }
        }
    }
}

// ---------------------------------------------------------------------------
extern "C" void kernel_launch(void* const* d_in, const int* in_sizes, int n_in,
                              void* d_out, int out_size) {
    const float* x    = (const float*)d_in[0];
    const float* wqkv = (const float*)d_in[1];
    const float* pos  = (const float*)d_in[2];
    const float* wout = (const float*)d_in[3];
    const float* bout = (const float*)d_in[4];
    float* out = (float*)d_out;

    cudaFuncSetAttribute(qkv_tc, cudaFuncAttributeMaxDynamicSharedMemorySize, SMEM_BYTES);
    cudaFuncSetAttribute(out_tc, cudaFuncAttributeMaxDynamicSharedMemorySize, SMEM_BYTES);

    bias_kernel<<<16, 256>>>(pos);
    qkv_tc<<<MTOT / 64, 128, SMEM_BYTES>>>(x, wqkv);
    attn_mma<<<BATCH * NWIN * HEADS, 128>>>();
    out_tc<<<MTOT / 64, 128, SMEM_BYTES>>>(wout, bout, out);
}

// round 11
// speedup vs baseline: 2.1017x; 1.5427x over previous
#include <cuda_runtime.h>
#include <cuda_fp16.h>
#include <cstdint>

#define HEADS 6
#define HD 32
#define CDIM 192
#define NQ 576
#define DISP 4
#define IMG 256
#define BATCH 4
#define TOK 64
#define NWIN 1024
#define MTOT (BATCH * IMG * IMG)
#define ATT_SCALE 0.17677669529663687f

// scratch (allocation-free rule: __device__ globals) — fp16 intermediates
__device__ __half g_qkv[(size_t)MTOT * NQ];     // ROLLED coords, [m, 576]
__device__ __half g_attn[(size_t)MTOT * CDIM];  // ROLLED coords, [m, 192]
__device__ float g_bias[TOK * TOK];

// ---------------------------------------------------------------------------
// mma.sync / ldmatrix helpers (fp16, fp32 accumulate)
// ---------------------------------------------------------------------------
__device__ __forceinline__ void mma_f16(float* c, const uint32_t* a, const uint32_t* b) {
    asm volatile(
        "mma.sync.aligned.m16n8k16.row.col.f32.f16.f16.f32 "
        "{%0,%1,%2,%3}, {%4,%5,%6,%7}, {%8,%9}, {%0,%1,%2,%3};"
        : "+f"(c[0]), "+f"(c[1]), "+f"(c[2]), "+f"(c[3])
        : "r"(a[0]), "r"(a[1]), "r"(a[2]), "r"(a[3]), "r"(b[0]), "r"(b[1]));
}
__device__ __forceinline__ uint32_t smem_u32(const void* p) {
    uint32_t a;
    asm("{ .reg .u64 t; cvta.to.shared.u64 t, %1; cvt.u32.u64 %0, t; }" : "=r"(a) : "l"(p));
    return a;
}
__device__ __forceinline__ void ldsm_x4(uint32_t* r, uint32_t addr) {
    asm volatile("ldmatrix.sync.aligned.m8n8.x4.shared.b16 {%0,%1,%2,%3}, [%4];"
                 : "=r"(r[0]), "=r"(r[1]), "=r"(r[2]), "=r"(r[3]) : "r"(addr));
}
__device__ __forceinline__ void ldsm_x4_t(uint32_t* r, uint32_t addr) {
    asm volatile("ldmatrix.sync.aligned.m8n8.x4.trans.shared.b16 {%0,%1,%2,%3}, [%4];"
                 : "=r"(r[0]), "=r"(r[1]), "=r"(r[2]), "=r"(r[3]) : "r"(addr));
}

// GEMM smem: BM=64 rows A + 64 rows B, 200 halves/row (400B ≡ 16 mod 128 -> ldsm conflict-free)
#define AST2 200
#define A_H (64 * AST2)
#define SMEM_BYTES (2 * A_H * 2)   // 51200 B

// ---------------------------------------------------------------------------
// Kernel 0: gather rel-pos bias table
// ---------------------------------------------------------------------------
__global__ void bias_kernel(const float* __restrict__ pos) {
    int idx = blockIdx.x * blockDim.x + threadIdx.x;
    if (idx < TOK * TOK) {
        int i = idx >> 6, j = idx & 63;
        g_bias[idx] = pos[((i >> 3) - (j >> 3) + 7) * 15 + ((i & 7) - (j & 7) + 7)];
    }
}

// ---------------------------------------------------------------------------
// Kernel 1: QKV GEMM (fp16 m16n8k16). BM=64, 128 thr, warp tile 32x32.
// Roll folded into A-load; g_qkv fp16, ROLLED coords.
// ---------------------------------------------------------------------------
__global__ __launch_bounds__(128) void qkv_tc(const float* __restrict__ x,
                                              const float* __restrict__ wqkv) {
    extern __shared__ __half smh[];
    __half* As = smh;
    __half* Bsh = smh + A_H;
    uint32_t sbase = smem_u32(smh);
    uint32_t bbase = sbase + A_H * 2;

    int tid = threadIdx.x;
    int wid = tid >> 5, lane = tid & 31;
    int warp_m = (wid >> 1) * 32;
    int warp_n = (wid & 1) * 32;
    int lr = lane >> 2, lc = lane & 3;
    int m0 = blockIdx.x * 64;

    // ldmatrix per-lane base byte-offsets (A non-trans; B non-trans on [n][k])
    uint32_t aoff0 = sbase + (uint32_t)((warp_m + (lane & 7) + ((lane >> 3) & 1) * 8) * (AST2 * 2)
                                        + ((lane >> 4) & 1) * 16);
    uint32_t aoff1 = aoff0 + 16 * (AST2 * 2);
    uint32_t boff0 = bbase + (uint32_t)((warp_n + (lane & 7) + ((lane >> 4) & 1) * 8) * (AST2 * 2)
                                        + ((lane >> 3) & 1) * 16);
    uint32_t boff1 = boff0 + 16 * (AST2 * 2);

    // A tile 64x192 fp32 -> fp16, roll folded in. 3072 float4 / 128 thr.
    #pragma unroll
    for (int j = 0; j < 24; j++) {
        int i = tid + j * 128;
        int r = i / 48, c4 = i % 48;
        int m = m0 + r;
        int bb = m >> 16, y = (m >> 8) & 255, xx = m & 255;
        int ys = (y + DISP) & 255, xs = (xx + DISP) & 255;
        float4 v = *(const float4*)(x + ((size_t)((bb * IMG + ys) * IMG + xs)) * CDIM + c4 * 4);
        __half2 h0 = __floats2half2_rn(v.x, v.y);
        __half2 h1 = __floats2half2_rn(v.z, v.w);
        *(__half2*)&As[r * AST2 + c4 * 4]     = h0;
        *(__half2*)&As[r * AST2 + c4 * 4 + 2] = h1;
    }

    for (int t = 0; t < 9; t++) {
        int n0 = t * 64;
        __syncthreads();   // prev-tile readers done (covers A-load on t=0 too)
        #pragma unroll
        for (int j = 0; j < 24; j++) {
            int i = tid + j * 128;
            int r = i / 48, c4 = i % 48;
            float4 v = *(const float4*)(wqkv + (size_t)(n0 + r) * CDIM + c4 * 4);
            __half2 h0 = __floats2half2_rn(v.x, v.y);
            __half2 h1 = __floats2half2_rn(v.z, v.w);
            *(__half2*)&Bsh[r * AST2 + c4 * 4]     = h0;
            *(__half2*)&Bsh[r * AST2 + c4 * 4 + 2] = h1;
        }
        __syncthreads();

        float acc[2][4][4] = {};
        #pragma unroll
        for (int kk = 0; kk < 12; kk++) {        // K=192 in k16 steps
            uint32_t kb = (uint32_t)(kk * 32);   // 16 halves
            uint32_t a0[4], a1[4], b0[4], b1[4];
            ldsm_x4(a0, aoff0 + kb);
            ldsm_x4(a1, aoff1 + kb);
            ldsm_x4(b0, boff0 + kb);
            ldsm_x4(b1, boff1 + kb);
            mma_f16(acc[0][0], a0, b0);     mma_f16(acc[0][1], a0, b0 + 2);
            mma_f16(acc[0][2], a0, b1);     mma_f16(acc[0][3], a0, b1 + 2);
            mma_f16(acc[1][0], a1, b0);     mma_f16(acc[1][1], a1, b0 + 2);
            mma_f16(acc[1][2], a1, b1);     mma_f16(acc[1][3], a1, b1 + 2);
        }

        // Epilogue: fp16 stores, natural [m][576] layout.
        #pragma unroll
        for (int mt = 0; mt < 2; mt++) {
            size_t r0 = (size_t)(m0 + warp_m + mt * 16 + lr) * NQ + n0 + warp_n;
            size_t r1 = r0 + 8 * NQ;
            #pragma unroll
            for (int nt = 0; nt < 4; nt++) {
                int col = nt * 8 + lc * 2;
                *(__half2*)(g_qkv + r0 + col) = __floats2half2_rn(acc[mt][nt][0], acc[mt][nt][1]);
                *(__half2*)(g_qkv + r1 + col) = __floats2half2_rn(acc[mt][nt][2], acc[mt][nt][3]);
            }
        }
    }
}

// ---------------------------------------------------------------------------
// Kernel 2: windowed attention, fp16 MMA. Block = (b, win, head), 128 thr,
// 4 warps x 16 q-rows. S = Q K^T, quad-shuffle softmax, O = P V (V via
// ldmatrix.trans). g_qkv already fp16 -> zero-conversion loads.
// ---------------------------------------------------------------------------
#define QST2 40    // Q/K/V row stride (halves): 80B ≡ 16 mod 128 -> conflict-free
#define PST2 72    // P row stride (halves): 144B ≡ 16 mod 128
#define BST 68     // bias row stride (fp32 words)

__global__ __launch_bounds__(128) void attn_mma() {
    __shared__ __half qkvs[3 * 64 * QST2];  // Q | K | V, each [64][40]
    __shared__ __half ps[64 * PST2];        // P [64][72]
    __shared__ float bsm[64 * BST];

    int bid = blockIdx.x;
    int head = bid % HEADS;
    int t2 = bid / HEADS;
    int win = t2 & (NWIN - 1);
    int bb = t2 >> 10;
    int wy = win >> 5, wx = win & 31;

    int tid = threadIdx.x;
    int wid = tid >> 5, lane = tid & 31;
    int lr = lane >> 2, lc = lane & 3;
    int r_base = wid * 16;

    uint32_t qbase = smem_u32(qkvs);
    uint32_t kbase = qbase + 64 * QST2 * 2;
    uint32_t vbase = kbase + 64 * QST2 * 2;
    uint32_t pbase = smem_u32(ps);

    // ---- load Q,K,V (fp16 raw 16B chunks) + bias ----
    #pragma unroll
    for (int l = 0; l < 6; l++) {
        int idx = tid + l * 128;            // 768 = 3 tensors x 64 tok x 4 chunks
        int tsel = idx >> 8;
        int rem = idx & 255;
        int j = rem >> 2, c = rem & 3;
        int y = wy * 8 + (j >> 3), xx = wx * 8 + (j & 7);
        size_t base = ((size_t)((bb * IMG + y) * IMG + xx)) * NQ + tsel * CDIM + head * HD + c * 8;
        *(uint4*)&qkvs[tsel * 64 * QST2 + j * QST2 + c * 8] = *(const uint4*)(g_qkv + base);
    }
    #pragma unroll
    for (int l = 0; l < 8; l++) {
        int w0 = (tid + l * 128) * 4;
        int row = w0 >> 6, col = w0 & 63;
        *(float4*)(bsm + row * BST + col) = *(const float4*)(g_bias + w0);
    }
    __syncthreads();

    // ---- S = Q K^T * scale + bias ----
    uint32_t qoff = qbase + (uint32_t)((r_base + (lane & 7) + ((lane >> 3) & 1) * 8) * (QST2 * 2)
                                       + ((lane >> 4) & 1) * 16);
    uint32_t qa[2][4];
    ldsm_x4(qa[0], qoff);
    ldsm_x4(qa[1], qoff + 32);

    float s[8][4] = {};
    #pragma unroll
    for (int p = 0; p < 4; p++) {          // nt pairs (16 kv tokens each)
        uint32_t koff = kbase + (uint32_t)((p * 16 + (lane & 7) + ((lane >> 4) & 1) * 8) * (QST2 * 2)
                                           + ((lane >> 3) & 1) * 16);
        #pragma unroll
        for (int kk = 0; kk < 2; kk++) {
            uint32_t kb[4];
            ldsm_x4(kb, koff + kk * 32);
            mma_f16(s[2 * p],     qa[kk], kb);
            mma_f16(s[2 * p + 1], qa[kk], kb + 2);
        }
    }

    int row0 = r_base + lr, row1 = r_base + lr + 8;
    #pragma unroll
    for (int nt = 0; nt < 8; nt++) {
        int col = nt * 8 + lc * 2;
        float2 b0 = *(const float2*)(bsm + row0 * BST + col);
        float2 b1 = *(const float2*)(bsm + row1 * BST + col);
        s[nt][0] = s[nt][0] * ATT_SCALE + b0.x;
        s[nt][1] = s[nt][1] * ATT_SCALE + b0.y;
        s[nt][2] = s[nt][2] * ATT_SCALE + b1.x;
        s[nt][3] = s[nt][3] * ATT_SCALE + b1.y;
    }

    // ---- softmax (rows row0/row1; reduce across quad lanes) ----
    float mx0 = -1e30f, mx1 = -1e30f;
    #pragma unroll
    for (int nt = 0; nt < 8; nt++) {
        mx0 = fmaxf(mx0, fmaxf(s[nt][0], s[nt][1]));
        mx1 = fmaxf(mx1, fmaxf(s[nt][2], s[nt][3]));
    }
    mx0 = fmaxf(mx0, __shfl_xor_sync(0xffffffff, mx0, 1));
    mx0 = fmaxf(mx0, __shfl_xor_sync(0xffffffff, mx0, 2));
    mx1 = fmaxf(mx1, __shfl_xor_sync(0xffffffff, mx1, 1));
    mx1 = fmaxf(mx1, __shfl_xor_sync(0xffffffff, mx1, 2));
    float sum0 = 0.f, sum1 = 0.f;
    #pragma unroll
    for (int nt = 0; nt < 8; nt++) {
        s[nt][0] = __expf(s[nt][0] - mx0); sum0 += s[nt][0];
        s[nt][1] = __expf(s[nt][1] - mx0); sum0 += s[nt][1];
        s[nt][2] = __expf(s[nt][2] - mx1); sum1 += s[nt][2];
        s[nt][3] = __expf(s[nt][3] - mx1); sum1 += s[nt][3];
    }
    sum0 += __shfl_xor_sync(0xffffffff, sum0, 1);
    sum0 += __shfl_xor_sync(0xffffffff, sum0, 2);
    sum1 += __shfl_xor_sync(0xffffffff, sum1, 1);
    sum1 += __shfl_xor_sync(0xffffffff, sum1, 2);
    float inv0 = 1.f / sum0, inv1 = 1.f / sum1;

    // ---- P (exp values) to smem as fp16; rows are warp-private ----
    #pragma unroll
    for (int nt = 0; nt < 8; nt++) {
        int col = nt * 8 + lc * 2;
        *(__half2*)&ps[row0 * PST2 + col] = __floats2half2_rn(s[nt][0], s[nt][1]);
        *(__half2*)&ps[row1 * PST2 + col] = __floats2half2_rn(s[nt][2], s[nt][3]);
    }
    __syncwarp();

    // ---- O = P V  (M=16, N=32, K=64); V via ldmatrix.trans on [token][d] ----
    uint32_t poff = pbase + (uint32_t)((r_base + (lane & 7) + ((lane >> 3) & 1) * 8) * (PST2 * 2)
                                       + ((lane >> 4) & 1) * 16);
    float o[4][4] = {};
    #pragma unroll
    for (int kk = 0; kk < 4; kk++) {       // 16 kv tokens per step
        uint32_t pa[4];
        ldsm_x4(pa, poff + kk * 32);
        #pragma unroll
        for (int q = 0; q < 2; q++) {      // n blocks of 16 (d-cols)
            uint32_t voff = vbase + (uint32_t)((kk * 16 + (lane & 7) + ((lane >> 3) & 1) * 8) * (QST2 * 2)
                                               + (q * 16 + ((lane >> 4) & 1) * 8) * 2);
            uint32_t vb[4];
            ldsm_x4_t(vb, voff);
            mma_f16(o[2 * q],     pa, vb);
            mma_f16(o[2 * q + 1], pa, vb + 2);
        }
    }

    // ---- epilogue: scale by 1/sum, write g_attn fp16 (rolled coords) ----
    {
        int i0 = r_base + lr;
        int y0 = wy * 8 + (i0 >> 3), x0 = wx * 8 + (i0 & 7);
        int i1 = i0 + 8;
        int y1 = wy * 8 + (i1 >> 3), x1 = wx * 8 + (i1 & 7);
        __half* p0 = g_attn + ((size_t)((bb * IMG + y0) * IMG + x0)) * CDIM + head * HD;
        __half* p1 = g_attn + ((size_t)((bb * IMG + y1) * IMG + x1)) * CDIM + head * HD;
        #pragma unroll
        for (int nt = 0; nt < 4; nt++) {
            int col = nt * 8 + lc * 2;
            *(__half2*)(p0 + col) = __floats2half2_rn(o[nt][0] * inv0, o[nt][1] * inv0);
            *(__half2*)(p1 + col) = __floats2half2_rn(o[nt][2] * inv1, o[nt][3] * inv1);
        }
    }
}

// ---------------------------------------------------------------------------
// Kernel 3: output projection (fp16 MMA) + bias; roll-back on store.
// A = g_attn (already fp16 -> raw copies); output fp32.
// ---------------------------------------------------------------------------
__global__ __launch_bounds__(128) void out_tc(const float* __restrict__ wout,
                                              const float* __restrict__ bout,
                                              float* __restrict__ out) {
    extern __shared__ __half smh[];
    __half* As = smh;
    __half* Bsh = smh + A_H;
    uint32_t sbase = smem_u32(smh);
    uint32_t bbase = sbase + A_H * 2;

    int tid = threadIdx.x;
    int wid = tid >> 5, lane = tid & 31;
    int warp_m = (wid >> 1) * 32;
    int warp_n = (wid & 1) * 32;
    int lr = lane >> 2, lc = lane & 3;
    int m0 = blockIdx.x * 64;

    uint32_t aoff0 = sbase + (uint32_t)((warp_m + (lane & 7) + ((lane >> 3) & 1) * 8) * (AST2 * 2)
                                        + ((lane >> 4) & 1) * 16);
    uint32_t aoff1 = aoff0 + 16 * (AST2 * 2);
    uint32_t boff0 = bbase + (uint32_t)((warp_n + (lane & 7) + ((lane >> 4) & 1) * 8) * (AST2 * 2)
                                        + ((lane >> 3) & 1) * 16);
    uint32_t boff1 = boff0 + 16 * (AST2 * 2);

    // A tile: raw fp16 16B copies. 64 rows x 24 chunks / 128 thr = 12 each.
    #pragma unroll
    for (int j = 0; j < 12; j++) {
        int i = tid + j * 128;
        int r = i / 24, c = i % 24;
        *(uint4*)&As[r * AST2 + c * 8] = *(const uint4*)(g_attn + (size_t)(m0 + r) * CDIM + c * 8);
    }

    for (int t = 0; t < 3; t++) {
        int n0 = t * 64;
        __syncthreads();
        #pragma unroll
        for (int j = 0; j < 24; j++) {
            int i = tid + j * 128;
            int r = i / 48, c4 = i % 48;
            float4 v = *(const float4*)(wout + (size_t)(n0 + r) * CDIM + c4 * 4);
            __half2 h0 = __floats2half2_rn(v.x, v.y);
            __half2 h1 = __floats2half2_rn(v.z, v.w);
            *(__half2*)&Bsh[r * AST2 + c4 * 4]     = h0;
            *(__half2*)&Bsh[r * AST2 + c4 * 4 + 2] = h1;
        }
        __syncthreads();

        float acc[2][4][4] = {};
        #pragma unroll
        for (int kk = 0; kk < 12; kk++) {
            uint32_t kb = (uint32_t)(kk * 32);
            uint32_t a0[4], a1[4], b0[4], b1[4];
            ldsm_x4(a0, aoff0 + kb);
            ldsm_x4(a1, aoff1 + kb);
            ldsm_x4(b0, boff0 + kb);
            ldsm_x4(b1, boff1 + kb);
            mma_f16(acc[0][0], a0, b0);     mma_f16(acc[0][1], a0, b0 + 2);
            mma_f16(acc[0][2], a0, b1);     mma_f16(acc[0][3], a0, b1 + 2);
            mma_f16(acc[1][0], a1, b0);     mma_f16(acc[1][1], a1, b0 + 2);
            mma_f16(acc[1][2], a1, b1);     mma_f16(acc[1][3], a1, b1 + 2);
        }

        #pragma unroll
        for (int mt = 0; mt < 2; mt++) {
            #pragma unroll
            for (int half = 0; half < 2; half++) {
                int m = m0 + warp_m + mt * 16 + lr + half * 8;
                int bb = m >> 16, y = (m >> 8) & 255, xx = m & 255;
                int yf = (y + DISP) & 255, xf = (xx + DISP) & 255;
                float* op = out + ((size_t)(bb * IMG + yf) * IMG + xf) * CDIM + n0 + warp_n;
                #pragma unroll
                for (int nt = 0; nt < 4; nt++) {
                    int col = nt * 8 + lc * 2;
                    float b0v = bout[n0 + warp_n + col];
                    float b1v = bout[n0 + warp_n + col + 1];
                    *(float2*)(op + col) = make_float2(acc[mt][nt][half * 2] + b0v,
                                                       acc[mt][nt][half * 2 + 1] + b1v);
                }
            }
        }
    }
}

// ---------------------------------------------------------------------------
extern "C" void kernel_launch(void* const* d_in, const int* in_sizes, int n_in,
                              void* d_out, int out_size) {
    const float* x    = (const float*)d_in[0];
    const float* wqkv = (const float*)d_in[1];
    const float* pos  = (const float*)d_in[2];
    const float* wout = (const float*)d_in[3];
    const float* bout = (const float*)d_in[4];
    float* out = (float*)d_out;

    cudaFuncSetAttribute(qkv_tc, cudaFuncAttributeMaxDynamicSharedMemorySize, SMEM_BYTES);
    cudaFuncSetAttribute(out_tc, cudaFuncAttributeMaxDynamicSharedMemorySize, SMEM_BYTES);

    bias_kernel<<<16, 256>>>(pos);
    qkv_tc<<<MTOT / 64, 128, SMEM_BYTES>>>(x, wqkv);
    attn_mma<<<BATCH * NWIN * HEADS, 128>>>();
    out_tc<<<MTOT / 64, 128, SMEM_BYTES>>>(wout, bout, out);
}

// round 12
// speedup vs baseline: 2.2118x; 1.0524x over previous
#include <cuda_runtime.h>
#include <cuda_fp16.h>
#include <cstdint>

#define HEADS 6
#define HD 32
#define CDIM 192
#define NQ 576
#define DISP 4
#define IMG 256
#define BATCH 4
#define TOK 64
#define NWIN 1024
#define MTOT (BATCH * IMG * IMG)
#define ATT_SCALE 0.17677669529663687f

// scratch (allocation-free rule: __device__ globals) — fp16 intermediates
__device__ __half g_qkv[(size_t)MTOT * NQ];     // ROLLED coords, [m, 576]
__device__ __half g_attn[(size_t)MTOT * CDIM];  // ROLLED coords, [m, 192]
__device__ float g_bias[TOK * TOK];
__device__ __half g_wqkv_h[NQ * CDIM];          // fp16 weights (pre-converted)
__device__ __half g_wout_h[CDIM * CDIM];

// ---------------------------------------------------------------------------
// mma.sync / ldmatrix helpers (fp16, fp32 accumulate)
// ---------------------------------------------------------------------------
__device__ __forceinline__ void mma_f16(float* c, const uint32_t* a, const uint32_t* b) {
    asm volatile(
        "mma.sync.aligned.m16n8k16.row.col.f32.f16.f16.f32 "
        "{%0,%1,%2,%3}, {%4,%5,%6,%7}, {%8,%9}, {%0,%1,%2,%3};"
        : "+f"(c[0]), "+f"(c[1]), "+f"(c[2]), "+f"(c[3])
        : "r"(a[0]), "r"(a[1]), "r"(a[2]), "r"(a[3]), "r"(b[0]), "r"(b[1]));
}
__device__ __forceinline__ uint32_t smem_u32(const void* p) {
    uint32_t a;
    asm("{ .reg .u64 t; cvta.to.shared.u64 t, %1; cvt.u32.u64 %0, t; }" : "=r"(a) : "l"(p));
    return a;
}
__device__ __forceinline__ void ldsm_x4(uint32_t* r, uint32_t addr) {
    asm volatile("ldmatrix.sync.aligned.m8n8.x4.shared.b16 {%0,%1,%2,%3}, [%4];"
                 : "=r"(r[0]), "=r"(r[1]), "=r"(r[2]), "=r"(r[3]) : "r"(addr));
}
__device__ __forceinline__ void ldsm_x4_t(uint32_t* r, uint32_t addr) {
    asm volatile("ldmatrix.sync.aligned.m8n8.x4.trans.shared.b16 {%0,%1,%2,%3}, [%4];"
                 : "=r"(r[0]), "=r"(r[1]), "=r"(r[2]), "=r"(r[3]) : "r"(addr));
}

// GEMM smem: BM=64 rows A + 64 rows B, 200 halves/row (400B ≡ 16 mod 128 -> ldsm conflict-free)
#define AST2 200
#define A_H (64 * AST2)
#define SMEM_BYTES (2 * A_H * 2)   // 51200 B

// ---------------------------------------------------------------------------
// Kernel 0a: gather rel-pos bias table;  0b: weights fp32 -> fp16
// ---------------------------------------------------------------------------
__global__ void bias_kernel(const float* __restrict__ pos) {
    int idx = blockIdx.x * blockDim.x + threadIdx.x;
    if (idx < TOK * TOK) {
        int i = idx >> 6, j = idx & 63;
        g_bias[idx] = pos[((i >> 3) - (j >> 3) + 7) * 15 + ((i & 7) - (j & 7) + 7)];
    }
}
__global__ void wconv_kernel(const float* __restrict__ wqkv, const float* __restrict__ wout) {
    int idx = blockIdx.x * blockDim.x + threadIdx.x;
    if (idx < NQ * CDIM)   g_wqkv_h[idx] = __float2half_rn(wqkv[idx]);
    if (idx < CDIM * CDIM) g_wout_h[idx] = __float2half_rn(wout[idx]);
}

// ---------------------------------------------------------------------------
// Kernel 1: QKV GEMM (fp16 m16n8k16). BM=64, 128 thr, warp tile 32x32.
// B tiles: raw fp16 copies from pre-converted weights.
// Roll folded into A-load; g_qkv fp16, ROLLED coords.
// ---------------------------------------------------------------------------
__global__ __launch_bounds__(128, 4) void qkv_tc(const float* __restrict__ x) {
    extern __shared__ __half smh[];
    __half* As = smh;
    __half* Bsh = smh + A_H;
    uint32_t sbase = smem_u32(smh);
    uint32_t bbase = sbase + A_H * 2;

    int tid = threadIdx.x;
    int wid = tid >> 5, lane = tid & 31;
    int warp_m = (wid >> 1) * 32;
    int warp_n = (wid & 1) * 32;
    int lr = lane >> 2, lc = lane & 3;
    int m0 = blockIdx.x * 64;

    uint32_t aoff0 = sbase + (uint32_t)((warp_m + (lane & 7) + ((lane >> 3) & 1) * 8) * (AST2 * 2)
                                        + ((lane >> 4) & 1) * 16);
    uint32_t aoff1 = aoff0 + 16 * (AST2 * 2);
    uint32_t boff0 = bbase + (uint32_t)((warp_n + (lane & 7) + ((lane >> 4) & 1) * 8) * (AST2 * 2)
                                        + ((lane >> 3) & 1) * 16);
    uint32_t boff1 = boff0 + 16 * (AST2 * 2);

    // A tile 64x192 fp32 -> fp16, roll folded in. 3072 float4 / 128 thr.
    #pragma unroll
    for (int j = 0; j < 24; j++) {
        int i = tid + j * 128;
        int r = i / 48, c4 = i % 48;
        int m = m0 + r;
        int bb = m >> 16, y = (m >> 8) & 255, xx = m & 255;
        int ys = (y + DISP) & 255, xs = (xx + DISP) & 255;
        float4 v = *(const float4*)(x + ((size_t)((bb * IMG + ys) * IMG + xs)) * CDIM + c4 * 4);
        *(__half2*)&As[r * AST2 + c4 * 4]     = __floats2half2_rn(v.x, v.y);
        *(__half2*)&As[r * AST2 + c4 * 4 + 2] = __floats2half2_rn(v.z, v.w);
    }

    for (int t = 0; t < 9; t++) {
        int n0 = t * 64;
        __syncthreads();   // prev-tile readers done (covers A-load on t=0 too)
        #pragma unroll
        for (int j = 0; j < 12; j++) {       // 64 rows x 24 16B-chunks, raw fp16
            int i = tid + j * 128;
            int r = i / 24, c = i % 24;
            *(uint4*)&Bsh[r * AST2 + c * 8] =
                *(const uint4*)(g_wqkv_h + (size_t)(n0 + r) * CDIM + c * 8);
        }
        __syncthreads();

        float acc[2][4][4] = {};
        #pragma unroll
        for (int kk = 0; kk < 12; kk++) {        // K=192 in k16 steps
            uint32_t kb = (uint32_t)(kk * 32);   // 16 halves
            uint32_t a0[4], a1[4], b0[4], b1[4];
            ldsm_x4(a0, aoff0 + kb);
            ldsm_x4(a1, aoff1 + kb);
            ldsm_x4(b0, boff0 + kb);
            ldsm_x4(b1, boff1 + kb);
            mma_f16(acc[0][0], a0, b0);     mma_f16(acc[0][1], a0, b0 + 2);
            mma_f16(acc[0][2], a0, b1);     mma_f16(acc[0][3], a0, b1 + 2);
            mma_f16(acc[1][0], a1, b0);     mma_f16(acc[1][1], a1, b0 + 2);
            mma_f16(acc[1][2], a1, b1);     mma_f16(acc[1][3], a1, b1 + 2);
        }

        // Epilogue: fp16 stores, natural [m][576] layout.
        #pragma unroll
        for (int mt = 0; mt < 2; mt++) {
            size_t r0 = (size_t)(m0 + warp_m + mt * 16 + lr) * NQ + n0 + warp_n;
            size_t r1 = r0 + 8 * NQ;
            #pragma unroll
            for (int nt = 0; nt < 4; nt++) {
                int col = nt * 8 + lc * 2;
                *(__half2*)(g_qkv + r0 + col) = __floats2half2_rn(acc[mt][nt][0], acc[mt][nt][1]);
                *(__half2*)(g_qkv + r1 + col) = __floats2half2_rn(acc[mt][nt][2], acc[mt][nt][3]);
            }
        }
    }
}

// ---------------------------------------------------------------------------
// Kernel 2: windowed attention, fp16 MMA (unchanged from round 11).
// ---------------------------------------------------------------------------
#define QST2 40    // Q/K/V row stride (halves): 80B ≡ 16 mod 128 -> conflict-free
#define PST2 72    // P row stride (halves): 144B ≡ 16 mod 128
#define BST 68     // bias row stride (fp32 words)

__global__ __launch_bounds__(128) void attn_mma() {
    __shared__ __half qkvs[3 * 64 * QST2];  // Q | K | V, each [64][40]
    __shared__ __half ps[64 * PST2];        // P [64][72]
    __shared__ float bsm[64 * BST];

    int bid = blockIdx.x;
    int head = bid % HEADS;
    int t2 = bid / HEADS;
    int win = t2 & (NWIN - 1);
    int bb = t2 >> 10;
    int wy = win >> 5, wx = win & 31;

    int tid = threadIdx.x;
    int wid = tid >> 5, lane = tid & 31;
    int lr = lane >> 2, lc = lane & 3;
    int r_base = wid * 16;

    uint32_t qbase = smem_u32(qkvs);
    uint32_t kbase = qbase + 64 * QST2 * 2;
    uint32_t vbase = kbase + 64 * QST2 * 2;
    uint32_t pbase = smem_u32(ps);

    // ---- load Q,K,V (fp16 raw 16B chunks) + bias ----
    #pragma unroll
    for (int l = 0; l < 6; l++) {
        int idx = tid + l * 128;            // 768 = 3 tensors x 64 tok x 4 chunks
        int tsel = idx >> 8;
        int rem = idx & 255;
        int j = rem >> 2, c = rem & 3;
        int y = wy * 8 + (j >> 3), xx = wx * 8 + (j & 7);
        size_t base = ((size_t)((bb * IMG + y) * IMG + xx)) * NQ + tsel * CDIM + head * HD + c * 8;
        *(uint4*)&qkvs[tsel * 64 * QST2 + j * QST2 + c * 8] = *(const uint4*)(g_qkv + base);
    }
    #pragma unroll
    for (int l = 0; l < 8; l++) {
        int w0 = (tid + l * 128) * 4;
        int row = w0 >> 6, col = w0 & 63;
        *(float4*)(bsm + row * BST + col) = *(const float4*)(g_bias + w0);
    }
    __syncthreads();

    // ---- S = Q K^T * scale + bias ----
    uint32_t qoff = qbase + (uint32_t)((r_base + (lane & 7) + ((lane >> 3) & 1) * 8) * (QST2 * 2)
                                       + ((lane >> 4) & 1) * 16);
    uint32_t qa[2][4];
    ldsm_x4(qa[0], qoff);
    ldsm_x4(qa[1], qoff + 32);

    float s[8][4] = {};
    #pragma unroll
    for (int p = 0; p < 4; p++) {          // nt pairs (16 kv tokens each)
        uint32_t koff = kbase + (uint32_t)((p * 16 + (lane & 7) + ((lane >> 4) & 1) * 8) * (QST2 * 2)
                                           + ((lane >> 3) & 1) * 16);
        #pragma unroll
        for (int kk = 0; kk < 2; kk++) {
            uint32_t kb[4];
            ldsm_x4(kb, koff + kk * 32);
            mma_f16(s[2 * p],     qa[kk], kb);
            mma_f16(s[2 * p + 1], qa[kk], kb + 2);
        }
    }

    int row0 = r_base + lr, row1 = r_base + lr + 8;
    #pragma unroll
    for (int nt = 0; nt < 8; nt++) {
        int col = nt * 8 + lc * 2;
        float2 b0 = *(const float2*)(bsm + row0 * BST + col);
        float2 b1 = *(const float2*)(bsm + row1 * BST + col);
        s[nt][0] = s[nt][0] * ATT_SCALE + b0.x;
        s[nt][1] = s[nt][1] * ATT_SCALE + b0.y;
        s[nt][2] = s[nt][2] * ATT_SCALE + b1.x;
        s[nt][3] = s[nt][3] * ATT_SCALE + b1.y;
    }

    // ---- softmax (rows row0/row1; reduce across quad lanes) ----
    float mx0 = -1e30f, mx1 = -1e30f;
    #pragma unroll
    for (int nt = 0; nt < 8; nt++) {
        mx0 = fmaxf(mx0, fmaxf(s[nt][0], s[nt][1]));
        mx1 = fmaxf(mx1, fmaxf(s[nt][2], s[nt][3]));
    }
    mx0 = fmaxf(mx0, __shfl_xor_sync(0xffffffff, mx0, 1));
    mx0 = fmaxf(mx0, __shfl_xor_sync(0xffffffff, mx0, 2));
    mx1 = fmaxf(mx1, __shfl_xor_sync(0xffffffff, mx1, 1));
    mx1 = fmaxf(mx1, __shfl_xor_sync(0xffffffff, mx1, 2));
    float sum0 = 0.f, sum1 = 0.f;
    #pragma unroll
    for (int nt = 0; nt < 8; nt++) {
        s[nt][0] = __expf(s[nt][0] - mx0); sum0 += s[nt][0];
        s[nt][1] = __expf(s[nt][1] - mx0); sum0 += s[nt][1];
        s[nt][2] = __expf(s[nt][2] - mx1); sum1 += s[nt][2];
        s[nt][3] = __expf(s[nt][3] - mx1); sum1 += s[nt][3];
    }
    sum0 += __shfl_xor_sync(0xffffffff, sum0, 1);
    sum0 += __shfl_xor_sync(0xffffffff, sum0, 2);
    sum1 += __shfl_xor_sync(0xffffffff, sum1, 1);
    sum1 += __shfl_xor_sync(0xffffffff, sum1, 2);
    float inv0 = 1.f / sum0, inv1 = 1.f / sum1;

    // ---- P (exp values) to smem as fp16; rows are warp-private ----
    #pragma unroll
    for (int nt = 0; nt < 8; nt++) {
        int col = nt * 8 + lc * 2;
        *(__half2*)&ps[row0 * PST2 + col] = __floats2half2_rn(s[nt][0], s[nt][1]);
        *(__half2*)&ps[row1 * PST2 + col] = __floats2half2_rn(s[nt][2], s[nt][3]);
    }
    __syncwarp();

    // ---- O = P V  (M=16, N=32, K=64); V via ldmatrix.trans on [token][d] ----
    uint32_t poff = pbase + (uint32_t)((r_base + (lane & 7) + ((lane >> 3) & 1) * 8) * (PST2 * 2)
                                       + ((lane >> 4) & 1) * 16);
    float o[4][4] = {};
    #pragma unroll
    for (int kk = 0; kk < 4; kk++) {       // 16 kv tokens per step
        uint32_t pa[4];
        ldsm_x4(pa, poff + kk * 32);
        #pragma unroll
        for (int q = 0; q < 2; q++) {      // n blocks of 16 (d-cols)
            uint32_t voff = vbase + (uint32_t)((kk * 16 + (lane & 7) + ((lane >> 3) & 1) * 8) * (QST2 * 2)
                                               + (q * 16 + ((lane >> 4) & 1) * 8) * 2);
            uint32_t vb[4];
            ldsm_x4_t(vb, voff);
            mma_f16(o[2 * q],     pa, vb);
            mma_f16(o[2 * q + 1], pa, vb + 2);
        }
    }

    // ---- epilogue: scale by 1/sum, write g_attn fp16 (rolled coords) ----
    {
        int i0 = r_base + lr;
        int y0 = wy * 8 + (i0 >> 3), x0 = wx * 8 + (i0 & 7);
        int i1 = i0 + 8;
        int y1 = wy * 8 + (i1 >> 3), x1 = wx * 8 + (i1 & 7);
        __half* p0 = g_attn + ((size_t)((bb * IMG + y0) * IMG + x0)) * CDIM + head * HD;
        __half* p1 = g_attn + ((size_t)((bb * IMG + y1) * IMG + x1)) * CDIM + head * HD;
        #pragma unroll
        for (int nt = 0; nt < 4; nt++) {
            int col = nt * 8 + lc * 2;
            *(__half2*)(p0 + col) = __floats2half2_rn(o[nt][0] * inv0, o[nt][1] * inv0);
            *(__half2*)(p1 + col) = __floats2half2_rn(o[nt][2] * inv1, o[nt][3] * inv1);
        }
    }
}

// ---------------------------------------------------------------------------
// Kernel 3: output projection (fp16 MMA) + bias; roll-back on store.
// A = g_attn, B = g_wout_h (both fp16 -> raw copies); output fp32.
// ---------------------------------------------------------------------------
__global__ __launch_bounds__(128, 4) void out_tc(const float* __restrict__ bout,
                                                 float* __restrict__ out) {
    extern __shared__ __half smh[];
    __half* As = smh;
    __half* Bsh = smh + A_H;
    uint32_t sbase = smem_u32(smh);
    uint32_t bbase = sbase + A_H * 2;

    int tid = threadIdx.x;
    int wid = tid >> 5, lane = tid & 31;
    int warp_m = (wid >> 1) * 32;
    int warp_n = (wid & 1) * 32;
    int lr = lane >> 2, lc = lane & 3;
    int m0 = blockIdx.x * 64;

    uint32_t aoff0 = sbase + (uint32_t)((warp_m + (lane & 7) + ((lane >> 3) & 1) * 8) * (AST2 * 2)
                                        + ((lane >> 4) & 1) * 16);
    uint32_t aoff1 = aoff0 + 16 * (AST2 * 2);
    uint32_t boff0 = bbase + (uint32_t)((warp_n + (lane & 7) + ((lane >> 4) & 1) * 8) * (AST2 * 2)
                                        + ((lane >> 3) & 1) * 16);
    uint32_t boff1 = boff0 + 16 * (AST2 * 2);

    // A tile: raw fp16 16B copies.
    #pragma unroll
    for (int j = 0; j < 12; j++) {
        int i = tid + j * 128;
        int r = i / 24, c = i % 24;
        *(uint4*)&As[r * AST2 + c * 8] = *(const uint4*)(g_attn + (size_t)(m0 + r) * CDIM + c * 8);
    }

    for (int t = 0; t < 3; t++) {
        int n0 = t * 64;
        __syncthreads();
        #pragma unroll
        for (int j = 0; j < 12; j++) {     // raw fp16 B tile
            int i = tid + j * 128;
            int r = i / 24, c = i % 24;
            *(uint4*)&Bsh[r * AST2 + c * 8] =
                *(const uint4*)(g_wout_h + (size_t)(n0 + r) * CDIM + c * 8);
        }
        __syncthreads();

        float acc[2][4][4] = {};
        #pragma unroll
        for (int kk = 0; kk < 12; kk++) {
            uint32_t kb = (uint32_t)(kk * 32);
            uint32_t a0[4], a1[4], b0[4], b1[4];
            ldsm_x4(a0, aoff0 + kb);
            ldsm_x4(a1, aoff1 + kb);
            ldsm_x4(b0, boff0 + kb);
            ldsm_x4(b1, boff1 + kb);
            mma_f16(acc[0][0], a0, b0);     mma_f16(acc[0][1], a0, b0 + 2);
            mma_f16(acc[0][2], a0, b1);     mma_f16(acc[0][3], a0, b1 + 2);
            mma_f16(acc[1][0], a1, b0);     mma_f16(acc[1][1], a1, b0 + 2);
            mma_f16(acc[1][2], a1, b1);     mma_f16(acc[1][3], a1, b1 + 2);
        }

        #pragma unroll
        for (int mt = 0; mt < 2; mt++) {
            #pragma unroll
            for (int half = 0; half < 2; half++) {
                int m = m0 + warp_m + mt * 16 + lr + half * 8;
                int bb = m >> 16, y = (m >> 8) & 255, xx = m & 255;
                int yf = (y + DISP) & 255, xf = (xx + DISP) & 255;
                float* op = out + ((size_t)(bb * IMG + yf) * IMG + xf) * CDIM + n0 + warp_n;
                #pragma unroll
                for (int nt = 0; nt < 4; nt++) {
                    int col = nt * 8 + lc * 2;
                    float b0v = bout[n0 + warp_n + col];
                    float b1v = bout[n0 + warp_n + col + 1];
                    *(float2*)(op + col) = make_float2(acc[mt][nt][half * 2] + b0v,
                                                       acc[mt][nt][half * 2 + 1] + b1v);
                }
            }
        }
    }
}

// ---------------------------------------------------------------------------
extern "C" void kernel_launch(void* const* d_in, const int* in_sizes, int n_in,
                              void* d_out, int out_size) {
    const float* x    = (const float*)d_in[0];
    const float* wqkv = (const float*)d_in[1];
    const float* pos  = (const float*)d_in[2];
    const float* wout = (const float*)d_in[3];
    const float* bout = (const float*)d_in[4];
    float* out = (float*)d_out;

    cudaFuncSetAttribute(qkv_tc, cudaFuncAttributeMaxDynamicSharedMemorySize, SMEM_BYTES);
    cudaFuncSetAttribute(out_tc, cudaFuncAttributeMaxDynamicSharedMemorySize, SMEM_BYTES);

    bias_kernel<<<16, 256>>>(pos);
    wconv_kernel<<<(NQ * CDIM + 255) / 256, 256>>>(wqkv, wout);
    qkv_tc<<<MTOT / 64, 128, SMEM_BYTES>>>(x);
    attn_mma<<<BATCH * NWIN * HEADS, 128>>>();
    out_tc<<<MTOT / 64, 128, SMEM_BYTES>>>(bout, out);
}